// round 8
// baseline (speedup 1.0000x reference)
#include <cuda_runtime.h>
#include <cstdint>
#include <cstddef>

#define HW   409600       // 640*640
#define HW4  102400       // HW/4
#define HWW  12800        // HW/32 sel words per cb
#define NCB  16           // 2 classes * 8 batch
#define NK   5            // kernel maps per class
#define EPSV 1e-4
#define KP_BLOCKS (40 * 80)

// mode: 0 = FAST (nn==negtot => sel == tm>0.5), 1 = FALLBACK (mask = tm float),
//       2 = SLOW (exact radix-select threshold)
struct Scratch {
    int      pos[NCB];
    int      negtot[NCB];
    int      mode[NCB];
    unsigned done;                            // kern_pass completion counter
    double   ta[NCB],  tb_[NCB], tc_[NCB];    // text dice, binary tm>0.5 mask
    double   taf[NCB], tbf[NCB], tcf[NCB];    // text dice, float tm (fallback)
    double   ta2[NCB], tb2[NCB], tc2[NCB];    // text dice, thr-based (slow)
    double   ka[NCB][NK], kb[NCB][NK], kc[NCB][NK];
    unsigned selw[NCB][HWW];                  // NOT memset; fully overwritten
};
__device__ Scratch g;

__device__ __forceinline__ unsigned f2key(float f) {
    unsigned u = __float_as_uint(f);
    return (u & 0x80000000u) ? ~u : (u | 0x80000000u);
}
__device__ __forceinline__ float key2f(unsigned k) {
    unsigned u = (k & 0x80000000u) ? (k ^ 0x80000000u) : ~k;
    return __uint_as_float(u);
}
__device__ __forceinline__ float sigmoidf(float x) {
    return 1.0f / (1.0f + __expf(-x));
}
__device__ __forceinline__ float wredf(float v) {
#pragma unroll
    for (int o = 16; o; o >>= 1) v += __shfl_down_sync(0xffffffffu, v, o);
    return v;
}
__device__ __forceinline__ int wredi(int v) {
#pragma unroll
    for (int o = 16; o; o >>= 1) v += __shfl_down_sync(0xffffffffu, v, o);
    return v;
}

// ---------------------------------------------------------------------------
// text_pass: texts + gt_texts + tm for each (c,b).
//   -> pos/neg counts, FAST text dice sums (mask = tm>0.5),
//      packed sel bits (texts>0 & tm>0.5) for the kernel-channel pass.
// grid (100, 16) x 256 threads: exactly 4 iterations per thread.
// ---------------------------------------------------------------------------
__global__ void __launch_bounds__(256) text_pass(
    const float* __restrict__ outp, const float* __restrict__ lab,
    const float* __restrict__ tmask) {
    int cb = blockIdx.y;
    int c = cb >> 3, b = cb & 7;
    const float4* tx = (const float4*)outp + (size_t)(b * 12 + c * 6 + 5) * HW4;
    const float4* gt = (const float4*)lab  + (size_t)(b * 12 + c * 6 + 5) * HW4;
    const float4* tm = (const float4*)tmask + (size_t)b * HW4;
    unsigned* selw = g.selw[cb];

    int base = blockIdx.x * 256 + threadIdx.x;   // stride 25600, 4 trips
    float tA = 0.f, tB = 0.f, tC = 0.f;
    int pos = 0, neg = 0;

#pragma unroll
    for (int it = 0; it < 4; it++) {
        int i = base + it * 25600;
        float4 s4 = tx[i], g4 = gt[i], m4 = tm[i];
        float sv[4] = {s4.x, s4.y, s4.z, s4.w};
        float gv[4] = {g4.x, g4.y, g4.z, g4.w};
        float mv[4] = {m4.x, m4.y, m4.z, m4.w};
        unsigned nib = 0;
#pragma unroll
        for (int l = 0; l < 4; l++) {
            bool mp = mv[l] > 0.5f;
            bool gp = gv[l] > 0.5f;
            pos += (gp && mp) ? 1 : 0;
            neg += gp ? 0 : 1;
            nib |= (sv[l] > 0.0f && mp) ? (1u << l) : 0u;
            float m = mp ? 1.0f : 0.0f;
            float p = sigmoidf(sv[l]) * m;
            float t = gv[l] * m;
            tA = fmaf(p, t, tA);
            tB = fmaf(p, p, tB);
            tC = fmaf(t, t, tC);
        }
        // assemble 8 nibbles (8 consecutive float4 lanes = 32 px) into one word
        unsigned v = nib << ((i & 7) * 4);
        v |= __shfl_xor_sync(0xffffffffu, v, 1);
        v |= __shfl_xor_sync(0xffffffffu, v, 2);
        v |= __shfl_xor_sync(0xffffffffu, v, 4);
        if ((i & 7) == 0) selw[i >> 3] = v;
    }

    __shared__ double sacc[3];
    __shared__ int scnt[2];
    if (threadIdx.x < 3) sacc[threadIdx.x] = 0.0;
    if (threadIdx.x < 2) scnt[threadIdx.x] = 0;
    __syncthreads();
    int lane = threadIdx.x & 31;
    float ra = wredf(tA), rb = wredf(tB), rc = wredf(tC);
    int rp = wredi(pos), rn = wredi(neg);
    if (lane == 0) {
        atomicAdd(&sacc[0], (double)ra);
        atomicAdd(&sacc[1], (double)rb);
        atomicAdd(&sacc[2], (double)rc);
        atomicAdd(&scnt[0], rp);
        atomicAdd(&scnt[1], rn);
    }
    __syncthreads();
    if (threadIdx.x == 0) atomicAdd(&g.ta[cb],  sacc[0]);
    if (threadIdx.x == 1) atomicAdd(&g.tb_[cb], sacc[1]);
    if (threadIdx.x == 2) atomicAdd(&g.tc_[cb], sacc[2]);
    if (threadIdx.x == 3) atomicAdd(&g.pos[cb], scnt[0]);
    if (threadIdx.x == 4) atomicAdd(&g.negtot[cb], scnt[1]);
}

// ---------------------------------------------------------------------------
// slow_work: runs in kern_pass block (0,0) as a prefix, 256 threads.
// Computes mode per cb; mode 0 (always, on this distribution) costs 2 loads.
// mode 1: float-tm text sums. mode 2: exact radix select + thr-masked sums.
// ---------------------------------------------------------------------------
__device__ __noinline__ void slow_work(
    const float* __restrict__ outp, const float* __restrict__ lab,
    const float* __restrict__ tmask, int tid) {
    __shared__ int shist[256];
    __shared__ int sd, srank;
    __shared__ double swarp[8][3];

    for (int cb = 0; cb < NCB; cb++) {
        int pos = g.pos[cb], ntot = g.negtot[cb];
        int nn = min(pos * 3, ntot);
        int mode = (pos == 0 || nn == 0) ? 1 : (nn == ntot ? 0 : 2);
        if (tid == 0) g.mode[cb] = mode;
        if (mode == 0) continue;

        int c = cb >> 3, b = cb & 7;
        const float4* tx = (const float4*)outp + (size_t)(b * 12 + c * 6 + 5) * HW4;
        const float4* gt = (const float4*)lab  + (size_t)(b * 12 + c * 6 + 5) * HW4;
        const float4* tm = (const float4*)tmask + (size_t)b * HW4;

        float thr = 0.0f;
        if (mode == 2) {
            unsigned prefix = 0;
            int rank = nn;
            for (int r = 0; r < 4; r++) {
                int shift = 24 - 8 * r;
                shist[tid] = 0;
                __syncthreads();
                for (int i = tid; i < HW4; i += 256) {
                    float4 s4 = tx[i], g4 = gt[i];
                    float sv[4] = {s4.x, s4.y, s4.z, s4.w};
                    float gv[4] = {g4.x, g4.y, g4.z, g4.w};
#pragma unroll
                    for (int l = 0; l < 4; l++) {
                        if (gv[l] <= 0.5f) {
                            unsigned key = f2key(sv[l]);
                            if (r == 0 || (key >> (shift + 8)) == prefix)
                                atomicAdd(&shist[(key >> shift) & 0xFF], 1);
                        }
                    }
                }
                __syncthreads();
                if (tid == 0) {
                    int cum = 0, d = 0, rnew = rank;
                    for (int j = 255; j >= 0; j--) {
                        cum += shist[j];
                        if (cum >= rank) { d = j; rnew = rank - (cum - shist[j]); break; }
                    }
                    sd = d; srank = rnew;
                }
                __syncthreads();
                prefix = (prefix << 8) | (unsigned)sd;
                rank = srank;
                __syncthreads();
            }
            thr = key2f(prefix);
        }

        float A = 0.f, B = 0.f, C = 0.f;
        for (int i = tid; i < HW4; i += 256) {
            float4 s4 = tx[i], g4 = gt[i], m4 = tm[i];
            float sv[4] = {s4.x, s4.y, s4.z, s4.w};
            float gv[4] = {g4.x, g4.y, g4.z, g4.w};
            float mv[4] = {m4.x, m4.y, m4.z, m4.w};
#pragma unroll
            for (int l = 0; l < 4; l++) {
                float m;
                if (mode == 1) m = mv[l];
                else m = (((sv[l] >= thr) || (gv[l] > 0.5f)) && (mv[l] > 0.5f)) ? 1.0f : 0.0f;
                float p = sigmoidf(sv[l]) * m;
                float t = gv[l] * m;
                A = fmaf(p, t, A);
                B = fmaf(p, p, B);
                C = fmaf(t, t, C);
            }
        }
        int lane = tid & 31, wid = tid >> 5;
        float ra = wredf(A), rb = wredf(B), rc = wredf(C);
        if (lane == 0) { swarp[wid][0] = ra; swarp[wid][1] = rb; swarp[wid][2] = rc; }
        __syncthreads();
        if (tid == 0) {
            double a = 0, bb = 0, cc = 0;
            for (int w = 0; w < 8; w++) { a += swarp[w][0]; bb += swarp[w][1]; cc += swarp[w][2]; }
            if (mode == 1) { g.taf[cb] = a; g.tbf[cb] = bb; g.tcf[cb] = cc; }
            else           { g.ta2[cb] = a; g.tb2[cb] = bb; g.tc2[cb] = cc; }
        }
        __syncthreads();
    }
}

// ---------------------------------------------------------------------------
// finalize_tail: runs in the LAST kern_pass block to finish (256 threads).
// All inputs were written via L2 (atomics / plain stores from other blocks);
// this block never cached those lines in its L1.
// ---------------------------------------------------------------------------
__device__ __noinline__ void finalize_tail(float* __restrict__ res, int t) {
    __threadfence();
    __shared__ float sdk[NCB * NK];   // kernel dice terms per (cb,k)
    __shared__ float slt[NCB];        // text dice terms per cb

    if (t < NCB * NK) {
        int cb = t / NK, k = t % NK;
        double a = g.ka[cb][k], b = g.kb[cb][k], c = g.kc[cb][k];
        sdk[t] = (float)(1.0 - 2.0 * a / (b + c + 2.0 * EPSV));
    }
    if (t >= 96 && t < 96 + NCB) {
        int cb = t - 96;
        int m = g.mode[cb];
        double A, B, C;
        if (m == 0)      { A = g.ta[cb];  B = g.tb_[cb]; C = g.tc_[cb]; }
        else if (m == 1) { A = g.taf[cb]; B = g.tbf[cb]; C = g.tcf[cb]; }
        else             { A = g.ta2[cb]; B = g.tb2[cb]; C = g.tc2[cb]; }
        slt[cb] = (float)(1.0 - 2.0 * A / (B + C + 2.0 * EPSV));
    }
    __syncthreads();
    if (t == 0) {
        float lt_sum = 0.f, lk_sum = 0.f;
        for (int cb = 0; cb < NCB; cb++) {
            lt_sum += slt[cb];
            float dks = 0.f;
#pragma unroll
            for (int k = 0; k < NK; k++) dks += sdk[cb * NK + k];
            lk_sum += dks * (1.0f / (float)NK);
        }
        lt_sum *= (1.0f / (float)NCB);
        lk_sum *= (1.0f / (float)NCB);
        res[0] = 0.7f * lt_sum + 0.3f * lk_sum;
        res[1] = lt_sum;
        res[2] = lk_sum;
    }
}

// ---------------------------------------------------------------------------
// kern_pass: one (cb, k) channel pair per blockIdx.y (80 slices).
// Pure 2-stream read + broadcast sel word. grid (40, 80) x 256: 10 trips.
// Block (0,0) prepends the mode decision / slow path; the last block to
// finish appends the finalize reduction.
// ---------------------------------------------------------------------------
__global__ void __launch_bounds__(256) kern_pass(
    const float* __restrict__ outp, const float* __restrict__ lab,
    const float* __restrict__ tmask, float* __restrict__ res) {
    int tid = threadIdx.x;
    if (blockIdx.x == 0 && blockIdx.y == 0)
        slow_work(outp, lab, tmask, tid);

    int slice = blockIdx.y;
    int cb = slice / NK, k = slice % NK;
    int c = cb >> 3, b = cb & 7;
    const float4* pv4 = (const float4*)outp + (size_t)(b * 12 + c * 6 + k) * HW4;
    const float4* tv4 = (const float4*)lab  + (size_t)(b * 12 + c * 6 + k) * HW4;
    const unsigned* selw = g.selw[cb];

    int base = blockIdx.x * 256 + tid;   // stride 10240, 10 trips
    float A = 0.f, B = 0.f, C = 0.f;

#pragma unroll 5
    for (int it = 0; it < 10; it++) {
        int i = base + it * 10240;
        float4 p4 = pv4[i];
        float4 t4 = tv4[i];
        unsigned w = selw[i >> 3];
        unsigned nib = (w >> ((i & 7) * 4)) & 0xFu;
        float pv[4] = {p4.x, p4.y, p4.z, p4.w};
        float tv[4] = {t4.x, t4.y, t4.z, t4.w};
#pragma unroll
        for (int l = 0; l < 4; l++) {
            bool s = (nib >> l) & 1u;
            float p = s ? sigmoidf(pv[l]) : 0.0f;
            float t = s ? tv[l] : 0.0f;
            A = fmaf(p, t, A);
            B = fmaf(p, p, B);
            C = fmaf(t, t, C);
        }
    }

    __shared__ double sacc[3];
    __shared__ unsigned slast;
    if (tid < 3) sacc[tid] = 0.0;
    __syncthreads();
    int lane = tid & 31;
    float ra = wredf(A), rb = wredf(B), rc = wredf(C);
    if (lane == 0) {
        atomicAdd(&sacc[0], (double)ra);
        atomicAdd(&sacc[1], (double)rb);
        atomicAdd(&sacc[2], (double)rc);
    }
    __syncthreads();
    if (tid == 0) atomicAdd(&g.ka[cb][k], sacc[0]);
    if (tid == 1) atomicAdd(&g.kb[cb][k], sacc[1]);
    if (tid == 2) atomicAdd(&g.kc[cb][k], sacc[2]);

    // last-block-done: the final block performs the output reduction
    __threadfence();
    __syncthreads();
    if (tid == 0) slast = atomicAdd(&g.done, 1u);
    __syncthreads();
    if (slast == KP_BLOCKS - 1)
        finalize_tail(res, tid);
}

extern "C" void kernel_launch(void* const* d_in, const int* in_sizes, int n_in,
                              void* d_out, int out_size) {
    const float* outp = (const float*)d_in[0];
    const float* lab  = (const float*)d_in[1];
    const float* tm   = (const float*)d_in[2];
    float* res = (float*)d_out;

    void* gaddr = nullptr;
    cudaGetSymbolAddress(&gaddr, g);
    cudaMemsetAsync(gaddr, 0, offsetof(Scratch, selw));   // ~3.4 KB header

    dim3 gt(100, 16);
    text_pass<<<gt, 256>>>(outp, lab, tm);
    dim3 gk(40, 80);
    kern_pass<<<gk, 256>>>(outp, lab, tm, res);
}

// round 13
// speedup vs baseline: 1.2493x; 1.2493x over previous
#include <cuda_runtime.h>
#include <cstdint>
#include <cstddef>

#define HW   409600       // 640*640
#define HW4  102400       // HW/4
#define HWW  12800        // HW/32 sel words per cb
#define NCB  16           // 2 classes * 8 batch
#define NK   5            // kernel maps per class
#define EPSV 1e-4

// mode: 0 = FAST (nn==negtot => sel == tm>0.5), 1 = FALLBACK (mask = tm float),
//       2 = SLOW (exact radix-select threshold)
struct Scratch {
    int      pos[NCB];
    int      negtot[NCB];
    int      mode[NCB];
    unsigned done;                            // slow_final completion counter
    double   ta[NCB],  tb_[NCB], tc_[NCB];    // text dice, binary tm>0.5 mask
    double   taf[NCB], tbf[NCB], tcf[NCB];    // text dice, float tm (fallback)
    double   ta2[NCB], tb2[NCB], tc2[NCB];    // text dice, thr-based (slow)
    double   ka[NCB][NK], kb[NCB][NK], kc[NCB][NK];
    unsigned selw[NCB][HWW];                  // NOT memset; fully overwritten
};
__device__ Scratch g;

__device__ __forceinline__ unsigned f2key(float f) {
    unsigned u = __float_as_uint(f);
    return (u & 0x80000000u) ? ~u : (u | 0x80000000u);
}
__device__ __forceinline__ float key2f(unsigned k) {
    unsigned u = (k & 0x80000000u) ? (k ^ 0x80000000u) : ~k;
    return __uint_as_float(u);
}
// fast sigmoid: FMUL + MUFU.EX2 + FADD + MUFU.RCP (no IEEE div subroutine)
__device__ __forceinline__ float sigmoidf(float x) {
    return __fdividef(1.0f, 1.0f + __expf(-x));
}
__device__ __forceinline__ float wredf(float v) {
#pragma unroll
    for (int o = 16; o; o >>= 1) v += __shfl_down_sync(0xffffffffu, v, o);
    return v;
}
__device__ __forceinline__ int wredi(int v) {
#pragma unroll
    for (int o = 16; o; o >>= 1) v += __shfl_down_sync(0xffffffffu, v, o);
    return v;
}

// ---------------------------------------------------------------------------
// text_pass: texts + gt_texts + tm for each (c,b).
//   -> pos/neg counts, FAST text dice sums (mask = tm>0.5),
//      packed sel bits (texts>0 & tm>0.5) for the kernel-channel pass.
// grid (100, 16) x 256 threads: exactly 4 iterations per thread.
// ---------------------------------------------------------------------------
__global__ void __launch_bounds__(256) text_pass(
    const float* __restrict__ outp, const float* __restrict__ lab,
    const float* __restrict__ tmask) {
    int cb = blockIdx.y;
    int c = cb >> 3, b = cb & 7;
    const float4* tx = (const float4*)outp + (size_t)(b * 12 + c * 6 + 5) * HW4;
    const float4* gt = (const float4*)lab  + (size_t)(b * 12 + c * 6 + 5) * HW4;
    const float4* tm = (const float4*)tmask + (size_t)b * HW4;
    unsigned* selw = g.selw[cb];

    int base = blockIdx.x * 256 + threadIdx.x;   // stride 25600, 4 trips
    float tA = 0.f, tB = 0.f, tC = 0.f;
    int pos = 0, neg = 0;

#pragma unroll
    for (int it = 0; it < 4; it++) {
        int i = base + it * 25600;
        float4 s4 = tx[i], g4 = gt[i], m4 = tm[i];
        float sv[4] = {s4.x, s4.y, s4.z, s4.w};
        float gv[4] = {g4.x, g4.y, g4.z, g4.w};
        float mv[4] = {m4.x, m4.y, m4.z, m4.w};
        unsigned nib = 0;
#pragma unroll
        for (int l = 0; l < 4; l++) {
            bool mp = mv[l] > 0.5f;
            bool gp = gv[l] > 0.5f;
            pos += (gp && mp) ? 1 : 0;
            neg += gp ? 0 : 1;
            nib |= (sv[l] > 0.0f && mp) ? (1u << l) : 0u;
            float m = mp ? 1.0f : 0.0f;
            float p = sigmoidf(sv[l]) * m;
            float t = gv[l] * m;
            tA = fmaf(p, t, tA);
            tB = fmaf(p, p, tB);
            tC = fmaf(t, t, tC);
        }
        // assemble 8 nibbles (8 consecutive float4 lanes = 32 px) into one word
        unsigned v = nib << ((i & 7) * 4);
        v |= __shfl_xor_sync(0xffffffffu, v, 1);
        v |= __shfl_xor_sync(0xffffffffu, v, 2);
        v |= __shfl_xor_sync(0xffffffffu, v, 4);
        if ((i & 7) == 0) selw[i >> 3] = v;
    }

    __shared__ double sacc[3];
    __shared__ int scnt[2];
    if (threadIdx.x < 3) sacc[threadIdx.x] = 0.0;
    if (threadIdx.x < 2) scnt[threadIdx.x] = 0;
    __syncthreads();
    int lane = threadIdx.x & 31;
    float ra = wredf(tA), rb = wredf(tB), rc = wredf(tC);
    int rp = wredi(pos), rn = wredi(neg);
    if (lane == 0) {
        atomicAdd(&sacc[0], (double)ra);
        atomicAdd(&sacc[1], (double)rb);
        atomicAdd(&sacc[2], (double)rc);
        atomicAdd(&scnt[0], rp);
        atomicAdd(&scnt[1], rn);
    }
    __syncthreads();
    if (threadIdx.x == 0) atomicAdd(&g.ta[cb],  sacc[0]);
    if (threadIdx.x == 1) atomicAdd(&g.tb_[cb], sacc[1]);
    if (threadIdx.x == 2) atomicAdd(&g.tc_[cb], sacc[2]);
    if (threadIdx.x == 3) atomicAdd(&g.pos[cb], scnt[0]);
    if (threadIdx.x == 4) atomicAdd(&g.negtot[cb], scnt[1]);
}

// ---------------------------------------------------------------------------
// kern_pass: one (cb, k) channel pair per blockIdx.y (80 slices).
// Pure 2-stream read + broadcast sel word. grid (40, 80) x 256: 10 trips.
// NO fences, NO calls — keep this kernel a clean streamer (R8 lesson).
// ---------------------------------------------------------------------------
__global__ void __launch_bounds__(256) kern_pass(
    const float* __restrict__ outp, const float* __restrict__ lab) {
    int slice = blockIdx.y;
    int cb = slice / NK, k = slice % NK;
    int c = cb >> 3, b = cb & 7;
    const float4* pv4 = (const float4*)outp + (size_t)(b * 12 + c * 6 + k) * HW4;
    const float4* tv4 = (const float4*)lab  + (size_t)(b * 12 + c * 6 + k) * HW4;
    const unsigned* selw = g.selw[cb];

    int base = blockIdx.x * 256 + threadIdx.x;   // stride 10240, 10 trips
    float A = 0.f, B = 0.f, C = 0.f;

#pragma unroll 5
    for (int it = 0; it < 10; it++) {
        int i = base + it * 10240;
        float4 p4 = pv4[i];
        float4 t4 = tv4[i];
        unsigned w = selw[i >> 3];
        unsigned nib = (w >> ((i & 7) * 4)) & 0xFu;
        float pv[4] = {p4.x, p4.y, p4.z, p4.w};
        float tv[4] = {t4.x, t4.y, t4.z, t4.w};
#pragma unroll
        for (int l = 0; l < 4; l++) {
            bool s = (nib >> l) & 1u;
            float p = s ? sigmoidf(pv[l]) : 0.0f;
            float t = s ? tv[l] : 0.0f;
            A = fmaf(p, t, A);
            B = fmaf(p, p, B);
            C = fmaf(t, t, C);
        }
    }

    __shared__ double sacc[3];
    if (threadIdx.x < 3) sacc[threadIdx.x] = 0.0;
    __syncthreads();
    int lane = threadIdx.x & 31;
    float ra = wredf(A), rb = wredf(B), rc = wredf(C);
    if (lane == 0) {
        atomicAdd(&sacc[0], (double)ra);
        atomicAdd(&sacc[1], (double)rb);
        atomicAdd(&sacc[2], (double)rc);
    }
    __syncthreads();
    if (threadIdx.x == 0) atomicAdd(&g.ka[cb][k], sacc[0]);
    if (threadIdx.x == 1) atomicAdd(&g.kb[cb][k], sacc[1]);
    if (threadIdx.x == 2) atomicAdd(&g.kc[cb][k], sacc[2]);
}

// ---------------------------------------------------------------------------
// slow_final: 16 blocks (one per cb), 1024 threads.
// Per-cb: mode decision; mode 1 = float-tm text sums; mode 2 = exact 4-round
// radix select + thr-masked sums (statistically never runs).
// The LAST block to finish performs the final output reduction (fence cost
// is trivial at 16 blocks).
// ---------------------------------------------------------------------------
__global__ void __launch_bounds__(1024) slow_final(
    const float* __restrict__ outp, const float* __restrict__ lab,
    const float* __restrict__ tmask, float* __restrict__ res) {
    int cb = blockIdx.x;
    int tid = threadIdx.x;
    int pos = g.pos[cb], ntot = g.negtot[cb];
    int nn = min(pos * 3, ntot);
    int mode = (pos == 0 || nn == 0) ? 1 : (nn == ntot ? 0 : 2);
    if (tid == 0) g.mode[cb] = mode;

    __shared__ int shist[256];
    __shared__ int sd, srank;
    __shared__ double swarp[32][3];
    __shared__ unsigned slast;

    if (mode != 0) {
        int c = cb >> 3, b = cb & 7;
        const float4* tx = (const float4*)outp + (size_t)(b * 12 + c * 6 + 5) * HW4;
        const float4* gt = (const float4*)lab  + (size_t)(b * 12 + c * 6 + 5) * HW4;
        const float4* tm = (const float4*)tmask + (size_t)b * HW4;

        float thr = 0.0f;
        if (mode == 2) {
            unsigned prefix = 0;
            int rank = nn;
            for (int r = 0; r < 4; r++) {
                int shift = 24 - 8 * r;
                if (tid < 256) shist[tid] = 0;
                __syncthreads();
                for (int i = tid; i < HW4; i += 1024) {
                    float4 s4 = tx[i], g4 = gt[i];
                    float sv[4] = {s4.x, s4.y, s4.z, s4.w};
                    float gv[4] = {g4.x, g4.y, g4.z, g4.w};
#pragma unroll
                    for (int l = 0; l < 4; l++) {
                        if (gv[l] <= 0.5f) {
                            unsigned key = f2key(sv[l]);
                            if (r == 0 || (key >> (shift + 8)) == prefix)
                                atomicAdd(&shist[(key >> shift) & 0xFF], 1);
                        }
                    }
                }
                __syncthreads();
                if (tid == 0) {
                    int cum = 0, d = 0, rnew = rank;
                    for (int j = 255; j >= 0; j--) {
                        cum += shist[j];
                        if (cum >= rank) { d = j; rnew = rank - (cum - shist[j]); break; }
                    }
                    sd = d; srank = rnew;
                }
                __syncthreads();
                prefix = (prefix << 8) | (unsigned)sd;
                rank = srank;
                __syncthreads();
            }
            thr = key2f(prefix);
        }

        float A = 0.f, B = 0.f, C = 0.f;
        for (int i = tid; i < HW4; i += 1024) {
            float4 s4 = tx[i], g4 = gt[i], m4 = tm[i];
            float sv[4] = {s4.x, s4.y, s4.z, s4.w};
            float gv[4] = {g4.x, g4.y, g4.z, g4.w};
            float mv[4] = {m4.x, m4.y, m4.z, m4.w};
#pragma unroll
            for (int l = 0; l < 4; l++) {
                float m;
                if (mode == 1) m = mv[l];
                else m = (((sv[l] >= thr) || (gv[l] > 0.5f)) && (mv[l] > 0.5f)) ? 1.0f : 0.0f;
                float p = sigmoidf(sv[l]) * m;
                float t = gv[l] * m;
                A = fmaf(p, t, A);
                B = fmaf(p, p, B);
                C = fmaf(t, t, C);
            }
        }
        int lane = tid & 31, wid = tid >> 5;
        float ra = wredf(A), rb = wredf(B), rc = wredf(C);
        if (lane == 0) { swarp[wid][0] = ra; swarp[wid][1] = rb; swarp[wid][2] = rc; }
        __syncthreads();
        if (tid == 0) {
            double a = 0, bb = 0, cc = 0;
            for (int w = 0; w < 32; w++) { a += swarp[w][0]; bb += swarp[w][1]; cc += swarp[w][2]; }
            if (mode == 1) { g.taf[cb] = a; g.tbf[cb] = bb; g.tcf[cb] = cc; }
            else           { g.ta2[cb] = a; g.tb2[cb] = bb; g.tc2[cb] = cc; }
        }
    }

    // ---- last-done block does the output reduction ----
    __threadfence();
    __syncthreads();
    if (tid == 0) slast = atomicAdd(&g.done, 1u);
    __syncthreads();
    if (slast != NCB - 1) return;
    __threadfence();

    __shared__ float sdk[NCB * NK];   // kernel dice terms per (cb,k)
    __shared__ float slt[NCB];        // text dice terms per cb
    int t = tid;
    if (t < NCB * NK) {
        int xcb = t / NK, k = t % NK;
        double a = g.ka[xcb][k], b = g.kb[xcb][k], c = g.kc[xcb][k];
        sdk[t] = (float)(1.0 - 2.0 * a / (b + c + 2.0 * EPSV));
    }
    if (t >= 96 && t < 96 + NCB) {
        int xcb = t - 96;
        int m = g.mode[xcb];
        double A, B, C;
        if (m == 0)      { A = g.ta[xcb];  B = g.tb_[xcb]; C = g.tc_[xcb]; }
        else if (m == 1) { A = g.taf[xcb]; B = g.tbf[xcb]; C = g.tcf[xcb]; }
        else             { A = g.ta2[xcb]; B = g.tb2[xcb]; C = g.tc2[xcb]; }
        slt[xcb] = (float)(1.0 - 2.0 * A / (B + C + 2.0 * EPSV));
    }
    __syncthreads();
    if (t == 0) {
        float lt_sum = 0.f, lk_sum = 0.f;
        for (int xcb = 0; xcb < NCB; xcb++) {
            lt_sum += slt[xcb];
            float dks = 0.f;
#pragma unroll
            for (int k = 0; k < NK; k++) dks += sdk[xcb * NK + k];
            lk_sum += dks * (1.0f / (float)NK);
        }
        lt_sum *= (1.0f / (float)NCB);
        lk_sum *= (1.0f / (float)NCB);
        res[0] = 0.7f * lt_sum + 0.3f * lk_sum;
        res[1] = lt_sum;
        res[2] = lk_sum;
    }
}

extern "C" void kernel_launch(void* const* d_in, const int* in_sizes, int n_in,
                              void* d_out, int out_size) {
    const float* outp = (const float*)d_in[0];
    const float* lab  = (const float*)d_in[1];
    const float* tm   = (const float*)d_in[2];
    float* res = (float*)d_out;

    void* gaddr = nullptr;
    cudaGetSymbolAddress(&gaddr, g);
    cudaMemsetAsync(gaddr, 0, offsetof(Scratch, selw));   // ~3.4 KB header

    dim3 gt(100, 16);
    text_pass<<<gt, 256>>>(outp, lab, tm);
    dim3 gk(40, 80);
    kern_pass<<<gk, 256>>>(outp, lab);
    slow_final<<<NCB, 1024>>>(outp, lab, tm, res);
}

// round 16
// speedup vs baseline: 1.3270x; 1.0621x over previous
#include <cuda_runtime.h>
#include <cstdint>
#include <cstddef>

#define HW   409600       // 640*640
#define HW4  102400       // HW/4
#define NCB  16           // 2 classes * 8 batch
#define NK   5            // kernel maps per class
#define EPSV 1e-4

// mode: 0 = FAST (nn==negtot => sel == tm>0.5), 1 = FALLBACK (mask = tm float),
//       2 = SLOW (exact radix-select threshold)
struct Scratch {
    int      pos[NCB];
    int      negtot[NCB];
    int      mode[NCB];
    unsigned done;                            // slow_final completion counter
    double   ta[NCB],  tb_[NCB], tc_[NCB];    // text dice, binary tm>0.5 mask
    double   taf[NCB], tbf[NCB], tcf[NCB];    // text dice, float tm (fallback)
    double   ta2[NCB], tb2[NCB], tc2[NCB];    // text dice, thr-based (slow)
    double   ka[NCB][NK], kb[NCB][NK], kc[NCB][NK];
    uint8_t  selb[NCB][HW4];                  // NOT zeroed; fully overwritten
};
__device__ Scratch g;   // static zero-init; header re-zeroed by slow_final

__device__ __forceinline__ unsigned f2key(float f) {
    unsigned u = __float_as_uint(f);
    return (u & 0x80000000u) ? ~u : (u | 0x80000000u);
}
__device__ __forceinline__ float key2f(unsigned k) {
    unsigned u = (k & 0x80000000u) ? (k ^ 0x80000000u) : ~k;
    return __uint_as_float(u);
}
__device__ __forceinline__ float sigmoidf(float x) {
    return __fdividef(1.0f, 1.0f + __expf(-x));
}
__device__ __forceinline__ float wredf(float v) {
#pragma unroll
    for (int o = 16; o; o >>= 1) v += __shfl_down_sync(0xffffffffu, v, o);
    return v;
}
__device__ __forceinline__ int wredi(int v) {
#pragma unroll
    for (int o = 16; o; o >>= 1) v += __shfl_down_sync(0xffffffffu, v, o);
    return v;
}

// ---------------------------------------------------------------------------
// text_pass: texts + gt_texts + tm for each (c,b).
//   -> pos/neg counts, FAST text dice sums (mask = tm>0.5),
//      per-float4 sel byte (texts>0 & tm>0.5) for the kernel-channel pass.
// grid (200, 16) x 256 threads: exactly 2 trips per thread; no cross-lane
// dependency in the loop body so all 6 float4 loads can batch.
// ---------------------------------------------------------------------------
__global__ void __launch_bounds__(256) text_pass(
    const float* __restrict__ outp, const float* __restrict__ lab,
    const float* __restrict__ tmask) {
    int cb = blockIdx.y;
    int c = cb >> 3, b = cb & 7;
    const float4* tx = (const float4*)outp + (size_t)(b * 12 + c * 6 + 5) * HW4;
    const float4* gt = (const float4*)lab  + (size_t)(b * 12 + c * 6 + 5) * HW4;
    const float4* tm = (const float4*)tmask + (size_t)b * HW4;
    uint8_t* selb = g.selb[cb];

    int base = blockIdx.x * 256 + threadIdx.x;   // stride 51200, 2 trips
    float tA = 0.f, tB = 0.f, tC = 0.f;
    int pos = 0, neg = 0;

#pragma unroll
    for (int it = 0; it < 2; it++) {
        int i = base + it * 51200;
        float4 s4 = tx[i], g4 = gt[i], m4 = tm[i];
        float sv[4] = {s4.x, s4.y, s4.z, s4.w};
        float gv[4] = {g4.x, g4.y, g4.z, g4.w};
        float mv[4] = {m4.x, m4.y, m4.z, m4.w};
        unsigned nib = 0;
#pragma unroll
        for (int l = 0; l < 4; l++) {
            bool mp = mv[l] > 0.5f;
            bool gp = gv[l] > 0.5f;
            pos += (gp && mp) ? 1 : 0;
            neg += gp ? 0 : 1;
            nib |= (sv[l] > 0.0f && mp) ? (1u << l) : 0u;
            float m = mp ? 1.0f : 0.0f;
            float p = sigmoidf(sv[l]) * m;
            float t = gv[l] * m;
            tA = fmaf(p, t, tA);
            tB = fmaf(p, p, tB);
            tC = fmaf(t, t, tC);
        }
        selb[i] = (uint8_t)nib;
    }

    __shared__ double sacc[3];
    __shared__ int scnt[2];
    if (threadIdx.x < 3) sacc[threadIdx.x] = 0.0;
    if (threadIdx.x < 2) scnt[threadIdx.x] = 0;
    __syncthreads();
    int lane = threadIdx.x & 31;
    float ra = wredf(tA), rb = wredf(tB), rc = wredf(tC);
    int rp = wredi(pos), rn = wredi(neg);
    if (lane == 0) {
        atomicAdd(&sacc[0], (double)ra);
        atomicAdd(&sacc[1], (double)rb);
        atomicAdd(&sacc[2], (double)rc);
        atomicAdd(&scnt[0], rp);
        atomicAdd(&scnt[1], rn);
    }
    __syncthreads();
    if (threadIdx.x == 0) atomicAdd(&g.ta[cb],  sacc[0]);
    if (threadIdx.x == 1) atomicAdd(&g.tb_[cb], sacc[1]);
    if (threadIdx.x == 2) atomicAdd(&g.tc_[cb], sacc[2]);
    if (threadIdx.x == 3) atomicAdd(&g.pos[cb], scnt[0]);
    if (threadIdx.x == 4) atomicAdd(&g.negtot[cb], scnt[1]);
}

// ---------------------------------------------------------------------------
// kern_pass: one (cb, k) channel pair per blockIdx.y (80 slices).
// Pure 2-stream read + 1-byte sel read (selb is L2-resident).
// grid (40, 80) x 256: 10 trips. NO fences, NO calls (R8 lesson).
// ---------------------------------------------------------------------------
__global__ void __launch_bounds__(256) kern_pass(
    const float* __restrict__ outp, const float* __restrict__ lab) {
    int slice = blockIdx.y;
    int cb = slice / NK, k = slice % NK;
    int c = cb >> 3, b = cb & 7;
    const float4* pv4 = (const float4*)outp + (size_t)(b * 12 + c * 6 + k) * HW4;
    const float4* tv4 = (const float4*)lab  + (size_t)(b * 12 + c * 6 + k) * HW4;
    const uint8_t* selb = g.selb[cb];

    int base = blockIdx.x * 256 + threadIdx.x;   // stride 10240, 10 trips
    float A = 0.f, B = 0.f, C = 0.f;

#pragma unroll 5
    for (int it = 0; it < 10; it++) {
        int i = base + it * 10240;
        float4 p4 = pv4[i];
        float4 t4 = tv4[i];
        unsigned nib = selb[i];
        float pv[4] = {p4.x, p4.y, p4.z, p4.w};
        float tv[4] = {t4.x, t4.y, t4.z, t4.w};
#pragma unroll
        for (int l = 0; l < 4; l++) {
            bool s = (nib >> l) & 1u;
            float p = s ? sigmoidf(pv[l]) : 0.0f;
            float t = s ? tv[l] : 0.0f;
            A = fmaf(p, t, A);
            B = fmaf(p, p, B);
            C = fmaf(t, t, C);
        }
    }

    __shared__ double sacc[3];
    if (threadIdx.x < 3) sacc[threadIdx.x] = 0.0;
    __syncthreads();
    int lane = threadIdx.x & 31;
    float ra = wredf(A), rb = wredf(B), rc = wredf(C);
    if (lane == 0) {
        atomicAdd(&sacc[0], (double)ra);
        atomicAdd(&sacc[1], (double)rb);
        atomicAdd(&sacc[2], (double)rc);
    }
    __syncthreads();
    if (threadIdx.x == 0) atomicAdd(&g.ka[cb][k], sacc[0]);
    if (threadIdx.x == 1) atomicAdd(&g.kb[cb][k], sacc[1]);
    if (threadIdx.x == 2) atomicAdd(&g.kc[cb][k], sacc[2]);
}

// ---------------------------------------------------------------------------
// slow_final: 16 blocks (one per cb), 1024 threads.
// Per-cb: mode decision; mode 1 = float-tm text sums; mode 2 = exact 4-round
// radix select + thr-masked sums (statistically never runs).
// The LAST block to finish does the output reduction, then re-zeroes the
// scratch header so the next graph replay starts clean (replaces memset node).
// ---------------------------------------------------------------------------
__global__ void __launch_bounds__(1024) slow_final(
    const float* __restrict__ outp, const float* __restrict__ lab,
    const float* __restrict__ tmask, float* __restrict__ res) {
    int cb = blockIdx.x;
    int tid = threadIdx.x;
    int pos = g.pos[cb], ntot = g.negtot[cb];
    int nn = min(pos * 3, ntot);
    int mode = (pos == 0 || nn == 0) ? 1 : (nn == ntot ? 0 : 2);
    if (tid == 0) g.mode[cb] = mode;

    __shared__ int shist[256];
    __shared__ int sd, srank;
    __shared__ double swarp[32][3];
    __shared__ unsigned slast;

    if (mode != 0) {
        int c = cb >> 3, b = cb & 7;
        const float4* tx = (const float4*)outp + (size_t)(b * 12 + c * 6 + 5) * HW4;
        const float4* gt = (const float4*)lab  + (size_t)(b * 12 + c * 6 + 5) * HW4;
        const float4* tm = (const float4*)tmask + (size_t)b * HW4;

        float thr = 0.0f;
        if (mode == 2) {
            unsigned prefix = 0;
            int rank = nn;
            for (int r = 0; r < 4; r++) {
                int shift = 24 - 8 * r;
                if (tid < 256) shist[tid] = 0;
                __syncthreads();
                for (int i = tid; i < HW4; i += 1024) {
                    float4 s4 = tx[i], g4 = gt[i];
                    float sv[4] = {s4.x, s4.y, s4.z, s4.w};
                    float gv[4] = {g4.x, g4.y, g4.z, g4.w};
#pragma unroll
                    for (int l = 0; l < 4; l++) {
                        if (gv[l] <= 0.5f) {
                            unsigned key = f2key(sv[l]);
                            if (r == 0 || (key >> (shift + 8)) == prefix)
                                atomicAdd(&shist[(key >> shift) & 0xFF], 1);
                        }
                    }
                }
                __syncthreads();
                if (tid == 0) {
                    int cum = 0, d = 0, rnew = rank;
                    for (int j = 255; j >= 0; j--) {
                        cum += shist[j];
                        if (cum >= rank) { d = j; rnew = rank - (cum - shist[j]); break; }
                    }
                    sd = d; srank = rnew;
                }
                __syncthreads();
                prefix = (prefix << 8) | (unsigned)sd;
                rank = srank;
                __syncthreads();
            }
            thr = key2f(prefix);
        }

        float A = 0.f, B = 0.f, C = 0.f;
        for (int i = tid; i < HW4; i += 1024) {
            float4 s4 = tx[i], g4 = gt[i], m4 = tm[i];
            float sv[4] = {s4.x, s4.y, s4.z, s4.w};
            float gv[4] = {g4.x, g4.y, g4.z, g4.w};
            float mv[4] = {m4.x, m4.y, m4.z, m4.w};
#pragma unroll
            for (int l = 0; l < 4; l++) {
                float m;
                if (mode == 1) m = mv[l];
                else m = (((sv[l] >= thr) || (gv[l] > 0.5f)) && (mv[l] > 0.5f)) ? 1.0f : 0.0f;
                float p = sigmoidf(sv[l]) * m;
                float t = gv[l] * m;
                A = fmaf(p, t, A);
                B = fmaf(p, p, B);
                C = fmaf(t, t, C);
            }
        }
        int lane = tid & 31, wid = tid >> 5;
        float ra = wredf(A), rb = wredf(B), rc = wredf(C);
        if (lane == 0) { swarp[wid][0] = ra; swarp[wid][1] = rb; swarp[wid][2] = rc; }
        __syncthreads();
        if (tid == 0) {
            double a = 0, bb = 0, cc = 0;
            for (int w = 0; w < 32; w++) { a += swarp[w][0]; bb += swarp[w][1]; cc += swarp[w][2]; }
            if (mode == 1) { g.taf[cb] = a; g.tbf[cb] = bb; g.tcf[cb] = cc; }
            else           { g.ta2[cb] = a; g.tb2[cb] = bb; g.tc2[cb] = cc; }
        }
    }

    // ---- last-done block: output reduction + scratch header reset ----
    __threadfence();
    __syncthreads();
    if (tid == 0) slast = atomicAdd(&g.done, 1u);
    __syncthreads();
    if (slast != NCB - 1) return;
    __threadfence();

    __shared__ float sdk[NCB * NK];   // kernel dice terms per (cb,k)
    __shared__ float slt[NCB];        // text dice terms per cb
    int t = tid;
    if (t < NCB * NK) {
        int xcb = t / NK, k = t % NK;
        double a = g.ka[xcb][k], b = g.kb[xcb][k], c = g.kc[xcb][k];
        sdk[t] = (float)(1.0 - 2.0 * a / (b + c + 2.0 * EPSV));
    }
    if (t >= 96 && t < 96 + NCB) {
        int xcb = t - 96;
        int m = g.mode[xcb];
        double A, B, C;
        if (m == 0)      { A = g.ta[xcb];  B = g.tb_[xcb]; C = g.tc_[xcb]; }
        else if (m == 1) { A = g.taf[xcb]; B = g.tbf[xcb]; C = g.tcf[xcb]; }
        else             { A = g.ta2[xcb]; B = g.tb2[xcb]; C = g.tc2[xcb]; }
        slt[xcb] = (float)(1.0 - 2.0 * A / (B + C + 2.0 * EPSV));
    }
    __syncthreads();
    if (t == 0) {
        float lt_sum = 0.f, lk_sum = 0.f;
        for (int xcb = 0; xcb < NCB; xcb++) {
            lt_sum += slt[xcb];
            float dks = 0.f;
#pragma unroll
            for (int k = 0; k < NK; k++) dks += sdk[xcb * NK + k];
            lk_sum += dks * (1.0f / (float)NK);
        }
        lt_sum *= (1.0f / (float)NCB);
        lk_sum *= (1.0f / (float)NCB);
        res[0] = 0.7f * lt_sum + 0.3f * lk_sum;
        res[1] = lt_sum;
        res[2] = lk_sum;
    }
    __syncthreads();
    // zero the scratch header (everything before selb) for the next replay
    {
        int nwords = (int)(offsetof(Scratch, selb) / 4);
        int* hdr = (int*)&g;
        for (int i = t; i < nwords; i += 1024) hdr[i] = 0;
    }
}

extern "C" void kernel_launch(void* const* d_in, const int* in_sizes, int n_in,
                              void* d_out, int out_size) {
    const float* outp = (const float*)d_in[0];
    const float* lab  = (const float*)d_in[1];
    const float* tm   = (const float*)d_in[2];
    float* res = (float*)d_out;

    dim3 gt(200, 16);
    text_pass<<<gt, 256>>>(outp, lab, tm);
    dim3 gk(40, 80);
    kern_pass<<<gk, 256>>>(outp, lab);
    slow_final<<<NCB, 1024>>>(outp, lab, tm, res);
}